// round 2
// baseline (speedup 1.0000x reference)
#include <cuda_runtime.h>
#include <cuda_bf16.h>

// GDLoss: elementwise Gaussian KL-distance loss over [N,5] xywhr boxes.
// R2: LDG.128-vectorized smem staging, 4 boxes/thread (1024 boxes/block).
// 176MB traffic -> target ~90% of achievable HBM.

#define TAU_F   1.0f
#define EPS_F   1e-6f
#define BLK     256
#define BPB     1024                 // boxes per block (4 per thread)
#define NF      (BPB * 5)            // floats per tensor per block = 5120
#define NV4     (NF / 4)             // float4s per tensor per block = 1280
#define V4PT    (NV4 / BLK)          // float4 loads per thread per tensor = 5

__device__ __forceinline__ float gd_loss_one(
    float px, float py, float pw, float ph, float prr,
    float tx, float ty, float tw, float th, float trr)
{
    pw = fminf(fmaxf(pw, 1e-7f), 1e7f);
    ph = fminf(fmaxf(ph, 1e-7f), 1e7f);
    tw = fminf(fmaxf(tw, 1e-7f), 1e7f);
    th = fminf(fmaxf(th, 1e-7f), 1e7f);

    float cp, spn, ct, stn;
    __sincosf(prr, &spn, &cp);
    __sincosf(trr, &stn, &ct);

    const float pa = 0.25f * pw * pw;
    const float pb = 0.25f * ph * ph;
    const float p11 = pa * cp * cp + pb * spn * spn;
    const float p12 = (pa - pb) * spn * cp;
    const float p22 = pa * spn * spn + pb * cp * cp;

    const float ta = 0.25f * tw * tw;
    const float tb = 0.25f * th * th;
    const float t11 = ta * ct * ct + tb * stn * stn;
    const float t12 = (ta - tb) * stn * ct;
    const float t22 = ta * stn * stn + tb * ct * ct;

    const float det_p = p11 * p22 - p12 * p12;
    const float det_t = t11 * t22 - t12 * t12;

    const float dx = px - tx;
    const float dy = py - ty;

    const float inv_det_t = __frcp_rn(det_t);

    const float term1 = (t22 * dx * dx - 2.0f * t12 * dx * dy + t11 * dy * dy) * inv_det_t;
    const float trace_term = (t22 * p11 - 2.0f * t12 * p12 + t11 * p22) * inv_det_t;
    const float term2 = trace_term + __logf(det_t * __frcp_rn(det_p));

    float dis = term1 + term2 - 2.0f;
    float kl = fmaxf(dis, EPS_F);
    return 1.0f - __frcp_rn(TAU_F + sqrtf(kl));
}

__global__ void __launch_bounds__(BLK) gd_loss_kernel(
    const float* __restrict__ pred,
    const float* __restrict__ target,
    float* __restrict__ out,
    int n)
{
    __shared__ float sp[NF];
    __shared__ float st[NF];

    const int tid = threadIdx.x;
    const long long blockBase = (long long)blockIdx.x * BPB;
    int nb = n - (int)blockBase;
    if (nb <= 0) return;
    if (nb > BPB) nb = BPB;

    const float* __restrict__ pbase = pred   + blockBase * 5;
    const float* __restrict__ tbase = target + blockBase * 5;

    if (nb == BPB) {
        // Full block: unguarded vectorized staging. 10 independent LDG.128.
        const float4* __restrict__ p4 = (const float4*)pbase;
        const float4* __restrict__ t4 = (const float4*)tbase;
        float4* __restrict__ sp4 = (float4*)sp;
        float4* __restrict__ st4 = (float4*)st;
        #pragma unroll
        for (int j = 0; j < V4PT; ++j)
            sp4[tid + j * BLK] = p4[tid + j * BLK];
        #pragma unroll
        for (int j = 0; j < V4PT; ++j)
            st4[tid + j * BLK] = t4[tid + j * BLK];
    } else {
        // Tail block (at most one): scalar guarded staging.
        const int nfloats = nb * 5;
        for (int i = tid; i < nfloats; i += BLK) {
            sp[i] = pbase[i];
            st[i] = tbase[i];
        }
    }
    __syncthreads();

    #pragma unroll
    for (int k = 0; k < BPB / BLK; ++k) {
        const int box = tid + k * BLK;
        if (box < nb) {
            const int b5 = box * 5;  // stride-5 smem: gcd(5,32)=1, conflict-free
            float loss = gd_loss_one(
                sp[b5 + 0], sp[b5 + 1], sp[b5 + 2], sp[b5 + 3], sp[b5 + 4],
                st[b5 + 0], st[b5 + 1], st[b5 + 2], st[b5 + 3], st[b5 + 4]);
            out[blockBase + box] = loss;
        }
    }
}

extern "C" void kernel_launch(void* const* d_in, const int* in_sizes, int n_in,
                              void* d_out, int out_size)
{
    const float* pred   = (const float*)d_in[0];
    const float* target = (const float*)d_in[1];
    // d_in[2] (weight) is unused by the reference computation (LOSS_WEIGHT=1).
    float* out = (float*)d_out;

    const int n = out_size;  // N boxes; output is [N,1] floats
    const int grid = (n + BPB - 1) / BPB;
    gd_loss_kernel<<<grid, BLK>>>(pred, target, out, n);
}